// round 14
// baseline (speedup 1.0000x reference)
#include <cuda_runtime.h>
#include <cuda_fp16.h>
#include <math.h>
#include <stdint.h>

#define BB   4
#define SS   2048
#define HH   1024
#define NHH  16
#define HDD  64
#define ROWS (BB*SS)            // 8192
#define TOT  (ROWS*HH)          // 8,388,608
#define LOG2E 1.4426950408889634f

// ---------------- device scratch (no allocs allowed) ----------------
__device__ __half g_Xh[TOT];
__device__ __half g_Wh[4][HH*HH];   // Wq, Wk, Wv, Wd (half)
__device__ __half g_Qh[TOT];
__device__ __half g_Kh[TOT];
__device__ __half g_Vh[TOT];
__device__ __half g_Ch[TOT];
__device__ float  g_Hd[TOT];

// ---------------- PTX helpers ----------------
__device__ __forceinline__ uint32_t smem_u32(const void* p) {
    return (uint32_t)__cvta_generic_to_shared(p);
}
__device__ __forceinline__ uint32_t h2_as_u32(__half2 h) {
    union { __half2 h2; uint32_t u; } cvt;
    cvt.h2 = h;
    return cvt.u;
}
#define CP_ASYNC(dst, src) asm volatile("cp.async.cg.shared.global [%0], [%1], 16;\n" :: "r"(dst), "l"(src))
#define CP_COMMIT()  asm volatile("cp.async.commit_group;\n")
#define CP_WAIT0()   asm volatile("cp.async.wait_group 0;\n")
#define CP_WAIT1()   asm volatile("cp.async.wait_group 1;\n")
#define CP_WAIT2()   asm volatile("cp.async.wait_group 2;\n")
#define CP_WAIT3()   asm volatile("cp.async.wait_group 3;\n")

__device__ __forceinline__ void ldsm4(uint32_t* r, uint32_t addr) {
    asm volatile("ldmatrix.sync.aligned.m8n8.x4.shared.b16 {%0,%1,%2,%3}, [%4];\n"
                 : "=r"(r[0]), "=r"(r[1]), "=r"(r[2]), "=r"(r[3]) : "r"(addr));
}
__device__ __forceinline__ void ldsm4t(uint32_t* r, uint32_t addr) {
    asm volatile("ldmatrix.sync.aligned.m8n8.x4.trans.shared.b16 {%0,%1,%2,%3}, [%4];\n"
                 : "=r"(r[0]), "=r"(r[1]), "=r"(r[2]), "=r"(r[3]) : "r"(addr));
}
__device__ __forceinline__ void mma16816(float* d, const uint32_t* a, const uint32_t* b) {
    asm volatile("mma.sync.aligned.m16n8k16.row.col.f32.f16.f16.f32 "
                 "{%0,%1,%2,%3}, {%4,%5,%6,%7}, {%8,%9}, {%0,%1,%2,%3};\n"
                 : "+f"(d[0]), "+f"(d[1]), "+f"(d[2]), "+f"(d[3])
                 : "r"(a[0]), "r"(a[1]), "r"(a[2]), "r"(a[3]), "r"(b[0]), "r"(b[1]));
}

// ---------------- fp32 -> fp16 conversions ----------------
__global__ void f2h_kernel(const float4* __restrict__ in, __half2* __restrict__ out, int n4) {
    int i = blockIdx.x * blockDim.x + threadIdx.x;
    if (i < n4) {
        float4 v = in[i];
        out[2*i + 0] = __floats2half2_rn(v.x, v.y);
        out[2*i + 1] = __floats2half2_rn(v.z, v.w);
    }
}
__global__ void f2h_w_kernel(const float4* __restrict__ w0, const float4* __restrict__ w1,
                             const float4* __restrict__ w2, const float4* __restrict__ w3,
                             __half2* __restrict__ out) {
    const float4* srcs[4] = { w0, w1, w2, w3 };
    const float4* src = srcs[blockIdx.y];
    __half2* dst = out + (size_t)blockIdx.y * (HH * HH / 2);
    int i = blockIdx.x * blockDim.x + threadIdx.x;
    float4 v = src[i];
    dst[2*i + 0] = __floats2half2_rn(v.x, v.y);
    dst[2*i + 1] = __floats2half2_rn(v.z, v.w);
}

// ---------------------------------------------------------------------------
// f16 GEMM, CUTLASS-style big tile: C[M,N] = A[M,K] @ B[K,N] + bias.
// Block tile 256x128, K-tile 32, 256 threads = 8 warps (4m x 2n), warp 64x64.
// 4-stage cp.async pipeline, 1 CTA/SM (~190 regs). blockIdx.z selects B/bias/C.
// smem: A [4][256][40] | B [4][32][136]  (proven padded layouts)
// ---------------------------------------------------------------------------
#define A_ST (256*40)
#define B_ST (32*136)

template<bool HALF_OUT>
__global__ __launch_bounds__(256, 1)
void gemm_big(const __half* __restrict__ A,
              const __half* __restrict__ B0, const __half* __restrict__ B1,
              const __half* __restrict__ B2,
              const float* __restrict__ bias0, const float* __restrict__ bias1,
              const float* __restrict__ bias2,
              void* __restrict__ C0, void* __restrict__ C1, void* __restrict__ C2)
{
    extern __shared__ __half gsm[];
    __half* As = gsm;               // [4][256][40]
    __half* Bs = gsm + 4 * A_ST;    // [4][32][136]

    const __half* B;
    const float* bias;
    void* Cout;
    if (blockIdx.z == 0)      { B = B0; bias = bias0; Cout = C0; }
    else if (blockIdx.z == 1) { B = B1; bias = bias1; Cout = C1; }
    else                      { B = B2; bias = bias2; Cout = C2; }

    const int tid  = threadIdx.x;
    const int lane = tid & 31;
    const int wid  = tid >> 5;     // 0..7
    const int g    = lane >> 2;
    const int t    = lane & 3;
    const int warp_m = wid >> 1;   // 0..3 (64 rows each)
    const int warp_n = wid & 1;    // 0..1 (64 cols each)
    const int bm = blockIdx.y * 256;
    const int bn = blockIdx.x * 128;
    const int NKT = HH / 32;       // 32

    // loads per kt: A 256 rows x 4 chunks (tid = row), B 512 chunks (2/thread)
    auto load_tile = [&](int kt, int st) {
        int k0 = kt * 32;
        const __half* asrc = A + (size_t)(bm + tid) * HH + k0;
        uint32_t adst = smem_u32(As + st * A_ST + tid * 40);
#pragma unroll
        for (int j = 0; j < 4; j++) CP_ASYNC(adst + j * 16, asrc + j * 8);
#pragma unroll
        for (int j = 0; j < 2; j++) {
            int idx = tid + j * 256;
            int r = idx >> 4, c = idx & 15;
            CP_ASYNC(smem_u32(Bs + st * B_ST + r * 136 + c * 8),
                     B + (size_t)(k0 + r) * HH + bn + c * 8);
        }
    };

    float acc[4][8][4];
#pragma unroll
    for (int mt = 0; mt < 4; mt++)
#pragma unroll
        for (int nt = 0; nt < 8; nt++)
#pragma unroll
            for (int i = 0; i < 4; i++) acc[mt][nt][i] = 0.0f;

    load_tile(0, 0); CP_COMMIT();
    load_tile(1, 1); CP_COMMIT();
    load_tile(2, 2); CP_COMMIT();
    CP_WAIT2();
    __syncthreads();

    const uint32_t a_base = smem_u32(As) + (warp_m * 64 + (lane & 15)) * 80 + (lane >> 4) * 16;
    const uint32_t b_base = smem_u32(Bs) + (((lane >> 3) & 1) * 8 + (lane & 7)) * 272 +
                            (warp_n * 64 + (lane >> 4) * 8) * 2;

    for (int kt = 0; kt < NKT; kt += 4) {
#pragma unroll
        for (int j = 0; j < 4; j++) {
            if (kt + j + 3 < NKT)      { load_tile(kt + j + 3, (j + 3) & 3); CP_COMMIT(); CP_WAIT3(); }
            else if (kt + j + 2 < NKT) { CP_WAIT2(); }
            else if (kt + j + 1 < NKT) { CP_WAIT1(); }
            else                       { CP_WAIT0(); }

            const uint32_t asb = a_base + j * (A_ST * 2);
            const uint32_t bsb = b_base + j * (B_ST * 2);
#pragma unroll
            for (int ks = 0; ks < 2; ks++) {
                uint32_t a[4][4], bq[4][4];
#pragma unroll
                for (int mt = 0; mt < 4; mt++)
                    ldsm4(a[mt], asb + mt * (16 * 80) + ks * 32);
#pragma unroll
                for (int np = 0; np < 4; np++)
                    ldsm4t(bq[np], bsb + ks * (16 * 272) + np * 32);
#pragma unroll
                for (int mt = 0; mt < 4; mt++)
#pragma unroll
                    for (int nt = 0; nt < 8; nt++)
                        mma16816(acc[mt][nt], a[mt], &bq[nt >> 1][2 * (nt & 1)]);
            }
            __syncthreads();
        }
    }

    // Epilogue
#pragma unroll
    for (int mt = 0; mt < 4; mt++) {
        int row = bm + warp_m * 64 + mt * 16 + g;
#pragma unroll
        for (int nt = 0; nt < 8; nt++) {
            int col = bn + warp_n * 64 + nt * 8 + 2 * t;
            float2 bv = *(const float2*)(bias + col);
            float x0 = acc[mt][nt][0] + bv.x, x1 = acc[mt][nt][1] + bv.y;
            float x2 = acc[mt][nt][2] + bv.x, x3 = acc[mt][nt][3] + bv.y;
            if (HALF_OUT) {
                __half* C = (__half*)Cout;
                *(__half2*)(C + (size_t)row * HH + col)       = __floats2half2_rn(x0, x1);
                *(__half2*)(C + (size_t)(row + 8) * HH + col) = __floats2half2_rn(x2, x3);
            } else {
                float* C = (float*)Cout;
                *(float2*)(C + (size_t)row * HH + col)       = make_float2(x0, x1);
                *(float2*)(C + (size_t)(row + 8) * HH + col) = make_float2(x2, x3);
            }
        }
    }
}

// ---------------------------------------------------------------------------
// Flash attention (PROVEN 502us version): f16 mma.sync, fp32 accum,
// register-resident P, no running max, h2exp2, l via P@ones mma,
// 4-stage cp.async K/V pipeline. Block = 8 warps x 16 Q rows, 2 CTAs/SM.
// ---------------------------------------------------------------------------
#define KV_ST   (64*72)
#define KV_ST_B (KV_ST*2)

__global__ __launch_bounds__(256, 2)
void attn16(const __half* __restrict__ Qg, const __half* __restrict__ Kg,
            const __half* __restrict__ Vg, const float* __restrict__ maskg,
            __half* __restrict__ Ctx)
{
    extern __shared__ char sm_raw[];
    __half* Qs  = (__half*)sm_raw;            // [128][72]
    __half* Ks  = Qs + 128 * 72;              // [4][64][72]
    __half* Vs  = Ks + 4 * KV_ST;             // [4][64][72]
    float*  Msk = (float*)(Vs + 4 * KV_ST);   // [4][64]

    const int tid  = threadIdx.x;
    const int lane = tid & 31;
    const int w    = tid >> 5;
    const int g    = lane >> 2;
    const int t    = lane & 3;
    const int qtile = blockIdx.x, h = blockIdx.y, b = blockIdx.z;
    const int tok0 = b * SS + qtile * 128;

    {
        int r = tid >> 1;
        const __half* src = Qg + (size_t)(tok0 + r) * HH + h * HDD;
        uint32_t dst = smem_u32(Qs + r * 72);
        int cb = (tid & 1) * 4;
#pragma unroll
        for (int j = 0; j < 4; j++) CP_ASYNC(dst + (cb + j) * 16, src + (cb + j) * 8);
    }

    auto load_tile = [&](int kt, int st) {
        int r = tid >> 2;
        int cb = (tid & 3) * 2;
        const __half* ks = Kg + (size_t)(b * SS + kt * 64 + r) * HH + h * HDD;
        const __half* vs = Vg + (size_t)(b * SS + kt * 64 + r) * HH + h * HDD;
        uint32_t kd = smem_u32(Ks + st * KV_ST + r * 72);
        uint32_t vd = smem_u32(Vs + st * KV_ST + r * 72);
#pragma unroll
        for (int j = 0; j < 2; j++) {
            CP_ASYNC(kd + (cb + j) * 16, ks + (cb + j) * 8);
            CP_ASYNC(vd + (cb + j) * 16, vs + (cb + j) * 8);
        }
        if (tid < 16)
            CP_ASYNC(smem_u32(Msk + st * 64 + tid * 4), maskg + (size_t)b * SS + kt * 64 + tid * 4);
    };

    load_tile(0, 0); CP_COMMIT();
    load_tile(1, 1); CP_COMMIT();
    load_tile(2, 2); CP_COMMIT();
    CP_WAIT2();
    __syncthreads();

    uint32_t qa[4][4];
    {
        uint32_t base = smem_u32(Qs + (16 * w + (lane & 15)) * 72 + (lane >> 4) * 8);
#pragma unroll
        for (int ks = 0; ks < 4; ks++) ldsm4(qa[ks], base + ks * 32);
    }

    float o[8][4];
#pragma unroll
    for (int nt = 0; nt < 8; nt++)
#pragma unroll
        for (int i = 0; i < 4; i++) o[nt][i] = 0.0f;
    float lacc[4] = {0.0f, 0.0f, 0.0f, 0.0f};
    const float SC2 = 0.125f * LOG2E;
    const uint32_t ONESH2 = 0x3C003C00u;
    const uint32_t onesb[2] = { ONESH2, ONESH2 };

    const uint32_t kfrag = smem_u32(Ks) + (lane & 7) * 144 + (lane >> 3) * 16;
    const uint32_t vfrag = smem_u32(Vs) + lane * 144;

    const int NKV = SS / 64;
    for (int kt = 0; kt < NKV; kt += 4) {
#pragma unroll
        for (int j = 0; j < 4; j++) {
            if (kt + j + 3 < NKV)      { load_tile(kt + j + 3, (j + 3) & 3); CP_COMMIT(); CP_WAIT3(); }
            else if (kt + j + 2 < NKV) { CP_WAIT2(); }
            else if (kt + j + 1 < NKV) { CP_WAIT1(); }
            else                       { CP_WAIT0(); }

            float s[8][4];
            const uint32_t kb0 = kfrag + j * KV_ST_B;
#pragma unroll
            for (int nt = 0; nt < 8; nt++) {
#pragma unroll
                for (int i = 0; i < 4; i++) s[nt][i] = 0.0f;
                uint32_t bb[8];
                ldsm4(&bb[0], kb0 + nt * (8 * 144));
                ldsm4(&bb[4], kb0 + nt * (8 * 144) + 64);
#pragma unroll
                for (int ks = 0; ks < 4; ks++) mma16816(s[nt], qa[ks], &bb[2 * ks]);
            }

            const float* mp = Msk + j * 64;
            uint32_t pk[8][2];
#pragma unroll
            for (int nt = 0; nt < 8; nt++) {
                float2 mk = *(const float2*)(mp + 8 * nt + 2 * t);
                float mkx = mk.x * LOG2E, mky = mk.y * LOG2E;
                float x0 = fmaf(s[nt][0], SC2, mkx);
                float x1 = fmaf(s[nt][1], SC2, mky);
                float x2 = fmaf(s[nt][2], SC2, mkx);
                float x3 = fmaf(s[nt][3], SC2, mky);
                pk[nt][0] = h2_as_u32(h2exp2(__floats2half2_rn(x0, x1)));
                pk[nt][1] = h2_as_u32(h2exp2(__floats2half2_rn(x2, x3)));
            }

            const uint32_t vb0 = vfrag + j * KV_ST_B;
#pragma unroll
            for (int nt = 0; nt < 8; nt++) {
                uint32_t vb[8];
                ldsm4t(&vb[0], vb0 + nt * 16);
                ldsm4t(&vb[4], vb0 + nt * 16 + 32 * 144);
#pragma unroll
                for (int kb = 0; kb < 4; kb++) {
                    uint32_t pa[4] = { pk[2*kb][0], pk[2*kb][1], pk[2*kb+1][0], pk[2*kb+1][1] };
                    mma16816(o[nt], pa, &vb[2 * kb]);
                }
            }
#pragma unroll
            for (int kb = 0; kb < 4; kb++) {
                uint32_t pa[4] = { pk[2*kb][0], pk[2*kb][1], pk[2*kb+1][0], pk[2*kb+1][1] };
                mma16816(lacc, pa, onesb);
            }
            __syncthreads();
        }
    }

    float ilo = 1.0f / lacc[0], ihi = 1.0f / lacc[2];
    int row = tok0 + 16 * w + g;
    __half* cb0 = Ctx + (size_t)row * HH + h * HDD + 2 * t;
    __half* cb1 = cb0 + (size_t)8 * HH;
#pragma unroll
    for (int nt = 0; nt < 8; nt++) {
        *(__half2*)(cb0 + 8 * nt) = __floats2half2_rn(o[nt][0] * ilo, o[nt][1] * ilo);
        *(__half2*)(cb1 + 8 * nt) = __floats2half2_rn(o[nt][2] * ihi, o[nt][3] * ihi);
    }
}

// ---------------------------------------------------------------------------
// LayerNorm(hidden) * gamma + beta + query
// ---------------------------------------------------------------------------
__global__ __launch_bounds__(256)
void ln_residual_kernel(const float* __restrict__ Hd, const float* __restrict__ X,
                        const float* __restrict__ gamma, const float* __restrict__ beta,
                        float* __restrict__ out)
{
    const int row = blockIdx.x;
    const int tid = threadIdx.x;
    const size_t base = (size_t)row * HH;

    float4 hv = ((const float4*)(Hd + base))[tid];
    float s  = hv.x + hv.y + hv.z + hv.w;
    float sq = hv.x * hv.x + hv.y * hv.y + hv.z * hv.z + hv.w * hv.w;
#pragma unroll
    for (int off = 16; off > 0; off >>= 1) {
        s  += __shfl_down_sync(0xffffffffu, s,  off);
        sq += __shfl_down_sync(0xffffffffu, sq, off);
    }
    __shared__ float ws[8], wsq[8], stats[2];
    int wid = tid >> 5, lane = tid & 31;
    if (lane == 0) { ws[wid] = s; wsq[wid] = sq; }
    __syncthreads();
    if (tid == 0) {
        float S = 0.0f, SQ = 0.0f;
#pragma unroll
        for (int i = 0; i < 8; i++) { S += ws[i]; SQ += wsq[i]; }
        float mean = S * (1.0f / HH);
        float var  = SQ * (1.0f / HH) - mean * mean;
        stats[0] = mean;
        stats[1] = rsqrtf(var + 1e-12f);
    }
    __syncthreads();
    float mean = stats[0], rstd = stats[1];

    float4 gv = ((const float4*)gamma)[tid];
    float4 bv = ((const float4*)beta)[tid];
    float4 xv = ((const float4*)(X + base))[tid];
    float4 ov;
    ov.x = (hv.x - mean) * rstd * gv.x + bv.x + xv.x;
    ov.y = (hv.y - mean) * rstd * gv.y + bv.y + xv.y;
    ov.z = (hv.z - mean) * rstd * gv.z + bv.z + xv.z;
    ov.w = (hv.w - mean) * rstd * gv.w + bv.w + xv.w;
    ((float4*)(out + base))[tid] = ov;
}

// ---------------------------------------------------------------------------
extern "C" void kernel_launch(void* const* d_in, const int* in_sizes, int n_in,
                              void* d_out, int out_size)
{
    const float* query = (const float*)d_in[0];
    const float* mask  = (const float*)d_in[1];
    const float* Wq    = (const float*)d_in[2];
    const float* bq    = (const float*)d_in[3];
    const float* Wk    = (const float*)d_in[4];
    const float* bk    = (const float*)d_in[5];
    const float* Wv    = (const float*)d_in[6];
    const float* bv    = (const float*)d_in[7];
    const float* Wd    = (const float*)d_in[8];
    const float* bd    = (const float*)d_in[9];
    const float* gamma = (const float*)d_in[10];
    const float* beta  = (const float*)d_in[11];
    float* out = (float*)d_out;

    __half *Xh, *Wh, *Qh, *Kh, *Vh, *Ch;
    float* Hp;
    cudaGetSymbolAddress((void**)&Xh,  g_Xh);
    cudaGetSymbolAddress((void**)&Wh,  g_Wh);
    cudaGetSymbolAddress((void**)&Qh,  g_Qh);
    cudaGetSymbolAddress((void**)&Kh,  g_Kh);
    cudaGetSymbolAddress((void**)&Vh,  g_Vh);
    cudaGetSymbolAddress((void**)&Ch,  g_Ch);
    cudaGetSymbolAddress((void**)&Hp,  g_Hd);

    __half* Wqh = Wh + 0 * (size_t)HH * HH;
    __half* Wkh = Wh + 1 * (size_t)HH * HH;
    __half* Wvh = Wh + 2 * (size_t)HH * HH;
    __half* Wdh = Wh + 3 * (size_t)HH * HH;

    // fp32 -> fp16 prep
    f2h_kernel<<<TOT / 4 / 256, 256>>>((const float4*)query, (__half2*)Xh, TOT / 4);
    f2h_w_kernel<<<dim3(HH * HH / 4 / 256, 4), 256>>>(
        (const float4*)Wq, (const float4*)Wk, (const float4*)Wv, (const float4*)Wd, (__half2*)Wh);

    const int gsmem = (4 * A_ST + 4 * B_ST) * 2;   // 116,736 B
    cudaFuncSetAttribute(gemm_big<true>,  cudaFuncAttributeMaxDynamicSharedMemorySize, gsmem);
    cudaFuncSetAttribute(gemm_big<false>, cudaFuncAttributeMaxDynamicSharedMemorySize, gsmem);

    // fused QKV projection (z selects W/bias/dst), 256x128 tiles
    dim3 gq(HH / 128, ROWS / 256, 3);   // (8, 32, 3)
    gemm_big<true><<<gq, 256, gsmem>>>(Xh, Wqh, Wkh, Wvh, bq, bk, bv, Qh, Kh, Vh);

    // attention (proven kernel)
    const size_t asmem = (size_t)(128 * 72 + 8 * KV_ST) * sizeof(__half) + 4 * 64 * sizeof(float);
    cudaFuncSetAttribute(attn16, cudaFuncAttributeMaxDynamicSharedMemorySize, (int)asmem);
    attn16<<<dim3(SS / 128, NHH, BB), 256, asmem>>>(Qh, Kh, Vh, mask, Ch);

    // output projection (float out)
    dim3 gg(HH / 128, ROWS / 256, 1);
    gemm_big<false><<<gg, 256, gsmem>>>(Ch, Wdh, nullptr, nullptr, bd, nullptr, nullptr,
                                        Hp, nullptr, nullptr);

    // LN + residual
    ln_residual_kernel<<<ROWS, 256>>>(Hp, query, gamma, beta, out);
}

// round 15
// speedup vs baseline: 1.1684x; 1.1684x over previous
#include <cuda_runtime.h>
#include <cuda_fp16.h>
#include <math.h>
#include <stdint.h>

#define BB   4
#define SS   2048
#define HH   1024
#define NHH  16
#define HDD  64
#define ROWS (BB*SS)            // 8192
#define TOT  (ROWS*HH)          // 8,388,608
#define LOG2E 1.4426950408889634f

// ---------------- device scratch (no allocs allowed) ----------------
__device__ __half g_Xh[TOT];
__device__ __half g_Wh[4][HH*HH];   // Wq, Wk, Wv, Wd (half)
__device__ __half g_Qh[TOT];
__device__ __half g_Kh[TOT];
__device__ __half g_Vh[TOT];
__device__ __half g_Ch[TOT];
__device__ float  g_Hd[TOT];

// ---------------- PTX helpers ----------------
__device__ __forceinline__ uint32_t smem_u32(const void* p) {
    return (uint32_t)__cvta_generic_to_shared(p);
}
__device__ __forceinline__ uint32_t h2_as_u32(__half2 h) {
    union { __half2 h2; uint32_t u; } cvt;
    cvt.h2 = h;
    return cvt.u;
}
#define CP_ASYNC(dst, src) asm volatile("cp.async.cg.shared.global [%0], [%1], 16;\n" :: "r"(dst), "l"(src))
#define CP_COMMIT()  asm volatile("cp.async.commit_group;\n")
#define CP_WAIT0()   asm volatile("cp.async.wait_group 0;\n")
#define CP_WAIT1()   asm volatile("cp.async.wait_group 1;\n")
#define CP_WAIT2()   asm volatile("cp.async.wait_group 2;\n")
#define CP_WAIT3()   asm volatile("cp.async.wait_group 3;\n")
#define CP_WAIT4()   asm volatile("cp.async.wait_group 4;\n")

__device__ __forceinline__ void ldsm4(uint32_t* r, uint32_t addr) {
    asm volatile("ldmatrix.sync.aligned.m8n8.x4.shared.b16 {%0,%1,%2,%3}, [%4];\n"
                 : "=r"(r[0]), "=r"(r[1]), "=r"(r[2]), "=r"(r[3]) : "r"(addr));
}
__device__ __forceinline__ void ldsm4t(uint32_t* r, uint32_t addr) {
    asm volatile("ldmatrix.sync.aligned.m8n8.x4.trans.shared.b16 {%0,%1,%2,%3}, [%4];\n"
                 : "=r"(r[0]), "=r"(r[1]), "=r"(r[2]), "=r"(r[3]) : "r"(addr));
}
__device__ __forceinline__ void mma16816(float* d, const uint32_t* a, const uint32_t* b) {
    asm volatile("mma.sync.aligned.m16n8k16.row.col.f32.f16.f16.f32 "
                 "{%0,%1,%2,%3}, {%4,%5,%6,%7}, {%8,%9}, {%0,%1,%2,%3};\n"
                 : "+f"(d[0]), "+f"(d[1]), "+f"(d[2]), "+f"(d[3])
                 : "r"(a[0]), "r"(a[1]), "r"(a[2]), "r"(a[3]), "r"(b[0]), "r"(b[1]));
}

// ---------------- fp32 -> fp16 conversions ----------------
__global__ void f2h_kernel(const float4* __restrict__ in, __half2* __restrict__ out, int n4) {
    int i = blockIdx.x * blockDim.x + threadIdx.x;
    if (i < n4) {
        float4 v = in[i];
        out[2*i + 0] = __floats2half2_rn(v.x, v.y);
        out[2*i + 1] = __floats2half2_rn(v.z, v.w);
    }
}
__global__ void f2h_w_kernel(const float4* __restrict__ w0, const float4* __restrict__ w1,
                             const float4* __restrict__ w2, const float4* __restrict__ w3,
                             __half2* __restrict__ out) {
    const float4* srcs[4] = { w0, w1, w2, w3 };
    const float4* src = srcs[blockIdx.y];
    __half2* dst = out + (size_t)blockIdx.y * (HH * HH / 2);
    int i = blockIdx.x * blockDim.x + threadIdx.x;
    float4 v = src[i];
    dst[2*i + 0] = __floats2half2_rn(v.x, v.y);
    dst[2*i + 1] = __floats2half2_rn(v.z, v.w);
}

// ---------------------------------------------------------------------------
// f16 GEMM (PROVEN R7 structure): C = A @ B + bias.
// Block 128x128, K-tile 32, 256 threads = 8 warps (2x4), warp 64x32, 2 CTAs/SM.
// ONLY change vs the 502us build: 5-stage cp.async pipeline (prefetch +4).
// blockIdx.z selects B/bias/C (QKV fusion).
// ---------------------------------------------------------------------------
#define A_ST (128*40)
#define B_ST (32*136)
#define NSTG 5

template<bool HALF_OUT>
__global__ __launch_bounds__(256, 2)
void gemm16(const __half* __restrict__ A,
            const __half* __restrict__ B0, const __half* __restrict__ B1, const __half* __restrict__ B2,
            const float* __restrict__ bias0, const float* __restrict__ bias1, const float* __restrict__ bias2,
            void* __restrict__ C0, void* __restrict__ C1, void* __restrict__ C2)
{
    extern __shared__ __half gsm[];
    __half* As = gsm;                  // [5][128][40]
    __half* Bs = gsm + NSTG * A_ST;    // [5][32][136]

    const __half* B;
    const float* bias;
    void* Cout;
    if (blockIdx.z == 0)      { B = B0; bias = bias0; Cout = C0; }
    else if (blockIdx.z == 1) { B = B1; bias = bias1; Cout = C1; }
    else                      { B = B2; bias = bias2; Cout = C2; }

    const int tid  = threadIdx.x;
    const int lane = tid & 31;
    const int wid  = tid >> 5;
    const int g    = lane >> 2;
    const int t    = lane & 3;
    const int warp_m = wid >> 2;
    const int warp_n = wid & 3;
    const int bm = blockIdx.y * 128;
    const int bn = blockIdx.x * 128;
    const int NKT = HH / 32;   // 32

    const int arow = tid >> 1;
    const int acb  = (tid & 1) * 2;
    const int brow = tid >> 4;
    const int bc   = tid & 15;

    auto load_tile = [&](int kt, int st) {
        int k0 = kt * 32;
        const __half* asrc = A + (size_t)(bm + arow) * HH + k0;
        uint32_t adst = smem_u32(As + st * A_ST + arow * 40);
        CP_ASYNC(adst + (acb + 0) * 16, asrc + (acb + 0) * 8);
        CP_ASYNC(adst + (acb + 1) * 16, asrc + (acb + 1) * 8);
        const __half* bsrc0 = B + (size_t)(k0 + brow) * HH + bn + bc * 8;
        const __half* bsrc1 = B + (size_t)(k0 + brow + 16) * HH + bn + bc * 8;
        CP_ASYNC(smem_u32(Bs + st * B_ST + brow * 136 + bc * 8), bsrc0);
        CP_ASYNC(smem_u32(Bs + st * B_ST + (brow + 16) * 136 + bc * 8), bsrc1);
    };

    float acc[4][4][4];
#pragma unroll
    for (int mt = 0; mt < 4; mt++)
#pragma unroll
        for (int nt = 0; nt < 4; nt++)
#pragma unroll
            for (int i = 0; i < 4; i++) acc[mt][nt][i] = 0.0f;

    load_tile(0, 0); CP_COMMIT();
    load_tile(1, 1); CP_COMMIT();
    load_tile(2, 2); CP_COMMIT();
    load_tile(3, 3); CP_COMMIT();
    CP_WAIT3();
    __syncthreads();

    const uint32_t a_base = smem_u32(As) + (warp_m * 64 + (lane & 15)) * 80 + (lane >> 4) * 16;
    const uint32_t b_base = smem_u32(Bs) + (((lane >> 3) & 1) * 8 + (lane & 7)) * 272 +
                            (warp_n * 32 + (lane >> 4) * 8) * 2;

    int st = 0, ld = 4;
    for (int kt = 0; kt < NKT; kt++) {
        if (kt + 4 < NKT)      { load_tile(kt + 4, ld); CP_COMMIT(); CP_WAIT4(); }
        else if (kt + 3 < NKT) { CP_WAIT3(); }
        else if (kt + 2 < NKT) { CP_WAIT2(); }
        else if (kt + 1 < NKT) { CP_WAIT1(); }
        else                   { CP_WAIT0(); }

        const uint32_t asb = a_base + st * (A_ST * 2);
        const uint32_t bsb = b_base + st * (B_ST * 2);
#pragma unroll
        for (int ks = 0; ks < 2; ks++) {
            uint32_t a[4][4], bq[8];
#pragma unroll
            for (int mt = 0; mt < 4; mt++)
                ldsm4(a[mt], asb + mt * (16 * 80) + ks * 32);
#pragma unroll
            for (int np = 0; np < 2; np++)
                ldsm4t(&bq[4 * np], bsb + ks * (16 * 272) + np * 32);
#pragma unroll
            for (int mt = 0; mt < 4; mt++)
#pragma unroll
                for (int nt = 0; nt < 4; nt++)
                    mma16816(acc[mt][nt], a[mt], &bq[2 * nt]);
        }
        __syncthreads();
        st = (st == NSTG - 1) ? 0 : st + 1;
        ld = (ld == NSTG - 1) ? 0 : ld + 1;
    }

    // Epilogue
#pragma unroll
    for (int mt = 0; mt < 4; mt++) {
        int row = bm + warp_m * 64 + mt * 16 + g;
#pragma unroll
        for (int nt = 0; nt < 4; nt++) {
            int col = bn + warp_n * 32 + nt * 8 + 2 * t;
            float2 bv = *(const float2*)(bias + col);
            float x0 = acc[mt][nt][0] + bv.x, x1 = acc[mt][nt][1] + bv.y;
            float x2 = acc[mt][nt][2] + bv.x, x3 = acc[mt][nt][3] + bv.y;
            if (HALF_OUT) {
                __half* C = (__half*)Cout;
                *(__half2*)(C + (size_t)row * HH + col)       = __floats2half2_rn(x0, x1);
                *(__half2*)(C + (size_t)(row + 8) * HH + col) = __floats2half2_rn(x2, x3);
            } else {
                float* C = (float*)Cout;
                *(float2*)(C + (size_t)row * HH + col)       = make_float2(x0, x1);
                *(float2*)(C + (size_t)(row + 8) * HH + col) = make_float2(x2, x3);
            }
        }
    }
}

// ---------------------------------------------------------------------------
// Flash attention (PROVEN 502us version, byte-identical): f16 mma.sync,
// fp32 accum, register-resident P, no running max, h2exp2, l via P@ones mma,
// 4-stage cp.async K/V pipeline. Block = 8 warps x 16 Q rows, 2 CTAs/SM.
// ---------------------------------------------------------------------------
#define KV_ST   (64*72)
#define KV_ST_B (KV_ST*2)

__global__ __launch_bounds__(256, 2)
void attn16(const __half* __restrict__ Qg, const __half* __restrict__ Kg,
            const __half* __restrict__ Vg, const float* __restrict__ maskg,
            __half* __restrict__ Ctx)
{
    extern __shared__ char sm_raw[];
    __half* Qs  = (__half*)sm_raw;            // [128][72]
    __half* Ks  = Qs + 128 * 72;              // [4][64][72]
    __half* Vs  = Ks + 4 * KV_ST;             // [4][64][72]
    float*  Msk = (float*)(Vs + 4 * KV_ST);   // [4][64]

    const int tid  = threadIdx.x;
    const int lane = tid & 31;
    const int w    = tid >> 5;
    const int g    = lane >> 2;
    const int t    = lane & 3;
    const int qtile = blockIdx.x, h = blockIdx.y, b = blockIdx.z;
    const int tok0 = b * SS + qtile * 128;

    {
        int r = tid >> 1;
        const __half* src = Qg + (size_t)(tok0 + r) * HH + h * HDD;
        uint32_t dst = smem_u32(Qs + r * 72);
        int cb = (tid & 1) * 4;
#pragma unroll
        for (int j = 0; j < 4; j++) CP_ASYNC(dst + (cb + j) * 16, src + (cb + j) * 8);
    }

    auto load_tile = [&](int kt, int st) {
        int r = tid >> 2;
        int cb = (tid & 3) * 2;
        const __half* ks = Kg + (size_t)(b * SS + kt * 64 + r) * HH + h * HDD;
        const __half* vs = Vg + (size_t)(b * SS + kt * 64 + r) * HH + h * HDD;
        uint32_t kd = smem_u32(Ks + st * KV_ST + r * 72);
        uint32_t vd = smem_u32(Vs + st * KV_ST + r * 72);
#pragma unroll
        for (int j = 0; j < 2; j++) {
            CP_ASYNC(kd + (cb + j) * 16, ks + (cb + j) * 8);
            CP_ASYNC(vd + (cb + j) * 16, vs + (cb + j) * 8);
        }
        if (tid < 16)
            CP_ASYNC(smem_u32(Msk + st * 64 + tid * 4), maskg + (size_t)b * SS + kt * 64 + tid * 4);
    };

    load_tile(0, 0); CP_COMMIT();
    load_tile(1, 1); CP_COMMIT();
    load_tile(2, 2); CP_COMMIT();
    CP_WAIT2();
    __syncthreads();

    uint32_t qa[4][4];
    {
        uint32_t base = smem_u32(Qs + (16 * w + (lane & 15)) * 72 + (lane >> 4) * 8);
#pragma unroll
        for (int ks = 0; ks < 4; ks++) ldsm4(qa[ks], base + ks * 32);
    }

    float o[8][4];
#pragma unroll
    for (int nt = 0; nt < 8; nt++)
#pragma unroll
        for (int i = 0; i < 4; i++) o[nt][i] = 0.0f;
    float lacc[4] = {0.0f, 0.0f, 0.0f, 0.0f};
    const float SC2 = 0.125f * LOG2E;
    const uint32_t ONESH2 = 0x3C003C00u;
    const uint32_t onesb[2] = { ONESH2, ONESH2 };

    const uint32_t kfrag = smem_u32(Ks) + (lane & 7) * 144 + (lane >> 3) * 16;
    const uint32_t vfrag = smem_u32(Vs) + lane * 144;

    const int NKV = SS / 64;
    for (int kt = 0; kt < NKV; kt += 4) {
#pragma unroll
        for (int j = 0; j < 4; j++) {
            if (kt + j + 3 < NKV)      { load_tile(kt + j + 3, (j + 3) & 3); CP_COMMIT(); CP_WAIT3(); }
            else if (kt + j + 2 < NKV) { CP_WAIT2(); }
            else if (kt + j + 1 < NKV) { CP_WAIT1(); }
            else                       { CP_WAIT0(); }

            float s[8][4];
            const uint32_t kb0 = kfrag + j * KV_ST_B;
#pragma unroll
            for (int nt = 0; nt < 8; nt++) {
#pragma unroll
                for (int i = 0; i < 4; i++) s[nt][i] = 0.0f;
                uint32_t bb[8];
                ldsm4(&bb[0], kb0 + nt * (8 * 144));
                ldsm4(&bb[4], kb0 + nt * (8 * 144) + 64);
#pragma unroll
                for (int ks = 0; ks < 4; ks++) mma16816(s[nt], qa[ks], &bb[2 * ks]);
            }

            const float* mp = Msk + j * 64;
            uint32_t pk[8][2];
#pragma unroll
            for (int nt = 0; nt < 8; nt++) {
                float2 mk = *(const float2*)(mp + 8 * nt + 2 * t);
                float mkx = mk.x * LOG2E, mky = mk.y * LOG2E;
                float x0 = fmaf(s[nt][0], SC2, mkx);
                float x1 = fmaf(s[nt][1], SC2, mky);
                float x2 = fmaf(s[nt][2], SC2, mkx);
                float x3 = fmaf(s[nt][3], SC2, mky);
                pk[nt][0] = h2_as_u32(h2exp2(__floats2half2_rn(x0, x1)));
                pk[nt][1] = h2_as_u32(h2exp2(__floats2half2_rn(x2, x3)));
            }

            const uint32_t vb0 = vfrag + j * KV_ST_B;
#pragma unroll
            for (int nt = 0; nt < 8; nt++) {
                uint32_t vb[8];
                ldsm4t(&vb[0], vb0 + nt * 16);
                ldsm4t(&vb[4], vb0 + nt * 16 + 32 * 144);
#pragma unroll
                for (int kb = 0; kb < 4; kb++) {
                    uint32_t pa[4] = { pk[2*kb][0], pk[2*kb][1], pk[2*kb+1][0], pk[2*kb+1][1] };
                    mma16816(o[nt], pa, &vb[2 * kb]);
                }
            }
#pragma unroll
            for (int kb = 0; kb < 4; kb++) {
                uint32_t pa[4] = { pk[2*kb][0], pk[2*kb][1], pk[2*kb+1][0], pk[2*kb+1][1] };
                mma16816(lacc, pa, onesb);
            }
            __syncthreads();
        }
    }

    float ilo = 1.0f / lacc[0], ihi = 1.0f / lacc[2];
    int row = tok0 + 16 * w + g;
    __half* cb0 = Ctx + (size_t)row * HH + h * HDD + 2 * t;
    __half* cb1 = cb0 + (size_t)8 * HH;
#pragma unroll
    for (int nt = 0; nt < 8; nt++) {
        *(__half2*)(cb0 + 8 * nt) = __floats2half2_rn(o[nt][0] * ilo, o[nt][1] * ilo);
        *(__half2*)(cb1 + 8 * nt) = __floats2half2_rn(o[nt][2] * ihi, o[nt][3] * ihi);
    }
}

// ---------------------------------------------------------------------------
// LayerNorm(hidden) * gamma + beta + query
// ---------------------------------------------------------------------------
__global__ __launch_bounds__(256)
void ln_residual_kernel(const float* __restrict__ Hd, const float* __restrict__ X,
                        const float* __restrict__ gamma, const float* __restrict__ beta,
                        float* __restrict__ out)
{
    const int row = blockIdx.x;
    const int tid = threadIdx.x;
    const size_t base = (size_t)row * HH;

    float4 hv = ((const float4*)(Hd + base))[tid];
    float s  = hv.x + hv.y + hv.z + hv.w;
    float sq = hv.x * hv.x + hv.y * hv.y + hv.z * hv.z + hv.w * hv.w;
#pragma unroll
    for (int off = 16; off > 0; off >>= 1) {
        s  += __shfl_down_sync(0xffffffffu, s,  off);
        sq += __shfl_down_sync(0xffffffffu, sq, off);
    }
    __shared__ float ws[8], wsq[8], stats[2];
    int wid = tid >> 5, lane = tid & 31;
    if (lane == 0) { ws[wid] = s; wsq[wid] = sq; }
    __syncthreads();
    if (tid == 0) {
        float S = 0.0f, SQ = 0.0f;
#pragma unroll
        for (int i = 0; i < 8; i++) { S += ws[i]; SQ += wsq[i]; }
        float mean = S * (1.0f / HH);
        float var  = SQ * (1.0f / HH) - mean * mean;
        stats[0] = mean;
        stats[1] = rsqrtf(var + 1e-12f);
    }
    __syncthreads();
    float mean = stats[0], rstd = stats[1];

    float4 gv = ((const float4*)gamma)[tid];
    float4 bv = ((const float4*)beta)[tid];
    float4 xv = ((const float4*)(X + base))[tid];
    float4 ov;
    ov.x = (hv.x - mean) * rstd * gv.x + bv.x + xv.x;
    ov.y = (hv.y - mean) * rstd * gv.y + bv.y + xv.y;
    ov.z = (hv.z - mean) * rstd * gv.z + bv.z + xv.z;
    ov.w = (hv.w - mean) * rstd * gv.w + bv.w + xv.w;
    ((float4*)(out + base))[tid] = ov;
}

// ---------------------------------------------------------------------------
extern "C" void kernel_launch(void* const* d_in, const int* in_sizes, int n_in,
                              void* d_out, int out_size)
{
    const float* query = (const float*)d_in[0];
    const float* mask  = (const float*)d_in[1];
    const float* Wq    = (const float*)d_in[2];
    const float* bq    = (const float*)d_in[3];
    const float* Wk    = (const float*)d_in[4];
    const float* bk    = (const float*)d_in[5];
    const float* Wv    = (const float*)d_in[6];
    const float* bv    = (const float*)d_in[7];
    const float* Wd    = (const float*)d_in[8];
    const float* bd    = (const float*)d_in[9];
    const float* gamma = (const float*)d_in[10];
    const float* beta  = (const float*)d_in[11];
    float* out = (float*)d_out;

    __half *Xh, *Wh, *Qh, *Kh, *Vh, *Ch;
    float* Hp;
    cudaGetSymbolAddress((void**)&Xh,  g_Xh);
    cudaGetSymbolAddress((void**)&Wh,  g_Wh);
    cudaGetSymbolAddress((void**)&Qh,  g_Qh);
    cudaGetSymbolAddress((void**)&Kh,  g_Kh);
    cudaGetSymbolAddress((void**)&Vh,  g_Vh);
    cudaGetSymbolAddress((void**)&Ch,  g_Ch);
    cudaGetSymbolAddress((void**)&Hp,  g_Hd);

    __half* Wqh = Wh + 0 * (size_t)HH * HH;
    __half* Wkh = Wh + 1 * (size_t)HH * HH;
    __half* Wvh = Wh + 2 * (size_t)HH * HH;
    __half* Wdh = Wh + 3 * (size_t)HH * HH;

    // fp32 -> fp16 prep
    f2h_kernel<<<TOT / 4 / 256, 256>>>((const float4*)query, (__half2*)Xh, TOT / 4);
    f2h_w_kernel<<<dim3(HH * HH / 4 / 256, 4), 256>>>(
        (const float4*)Wq, (const float4*)Wk, (const float4*)Wv, (const float4*)Wd, (__half2*)Wh);

    const int gsmem = NSTG * (A_ST + B_ST) * 2;   // 94,720 B (5 stages)
    cudaFuncSetAttribute(gemm16<true>,  cudaFuncAttributeMaxDynamicSharedMemorySize, gsmem);
    cudaFuncSetAttribute(gemm16<false>, cudaFuncAttributeMaxDynamicSharedMemorySize, gsmem);

    // fused QKV projection (z selects W/bias/dst)
    dim3 gq(HH / 128, ROWS / 128, 3);   // (8, 64, 3)
    gemm16<true><<<gq, 256, gsmem>>>(Xh, Wqh, Wkh, Wvh, bq, bk, bv, Qh, Kh, Vh);

    // attention (proven kernel)
    const size_t asmem = (size_t)(128 * 72 + 8 * KV_ST) * sizeof(__half) + 4 * 64 * sizeof(float);
    cudaFuncSetAttribute(attn16, cudaFuncAttributeMaxDynamicSharedMemorySize, (int)asmem);
    attn16<<<dim3(SS / 128, NHH, BB), 256, asmem>>>(Qh, Kh, Vh, mask, Ch);

    // output projection (float out)
    dim3 gg(HH / 128, ROWS / 128, 1);
    gemm16<false><<<gg, 256, gsmem>>>(Ch, Wdh, nullptr, nullptr, bd, nullptr, nullptr,
                                      Hp, nullptr, nullptr);

    // LN + residual
    ln_residual_kernel<<<ROWS, 256>>>(Hp, query, gamma, beta, out);
}